// round 6
// baseline (speedup 1.0000x reference)
#include <cuda_runtime.h>

#define BS  2
#define TT  12
#define B   24
#define N   150
#define DIN 64
#define F   128
#define NN  (N*N)     // 22500

#define RT   15       // output rows per GEMM tile
#define RTP  20       // padded row stride (4-way-conflict, LDS.128-aligned)
#define GT   10       // N/RT tiles
#define JT   80       // col-thread slots (j<75 active, 2 cols each)
#define NT   320      // threads per block
#define WFS  156      // WfS row stride (2-way staging conflict, LDS.64-aligned)
#define ABLK 100      // A-blocks: 25 tiles x 2 halves x 2 b
#define K1G  (1 + ABLK + GT*B)   // 341

// ---------------- scratch ----------------
__device__ float d_Ptmp[B*NN];
__device__ float d_A0[BS*NN];
__device__ float d_A1[BS*NN];
__device__ float d_wg[F];
__device__ float d_cg;
__device__ float d_cnt0[BS*N];
__device__ float d_cnt1[BS*N];
__device__ float d_u0[BS*N];
__device__ float d_u1[BS*N];

// ==== K1: wg fold | A0/A1 + counts + colsums | Ptmp GEMM  (one launch) ====
__global__ __launch_bounds__(NT) void k1(
        const float* __restrict__ H, const float* __restrict__ E,
        const float* __restrict__ adj,
        const float* __restrict__ WBw, const float* __restrict__ WBb,
        const float* __restrict__ Wfu, const float* __restrict__ aw) {
    __shared__ __align__(16) float sm[5184];   // 20.7 KB union
    int bid = blockIdx.x, tid = threadIdx.x;

    // ---- block 0: fold wg = WBw^T (aw[:64]+aw[64:]), cg ----
    if (bid == 0) {
        if (tid < F) {
            float acc = 0.f;
            #pragma unroll 8
            for (int h = 0; h < 64; h++)
                acc += WBw[h*F + tid] * (aw[h] + aw[h+64]);
            d_wg[tid] = acc;
        } else if (tid == F) {
            float acc = 0.f;
            for (int h = 0; h < 64; h++) acc += WBb[h] * (aw[h] + aw[h+64]);
            d_cg = acc;
        }
        return;
    }

    // ---- blocks 1..100: A-half blocks ----
    if (bid <= ABLK) {
        float* adjS = sm;            // 900
        float* colS = sm + 900;      // 3750
        int ab = bid - 1;
        int tile = ab % 25, half = (ab / 25) & 1, b = ab / 50;
        const float* a = adj + b*NN;
        int i0 = tile*6, j0 = half*75;

        for (int idx = tid; idx < 6*N; idx += NT) adjS[idx] = a[i0*N + idx];
        __syncthreads();

        if (tid < 6) {
            float c = 0.f;
            #pragma unroll 5
            for (int j = 0; j < 75; j++)
                c += (adjS[tid*N + j0 + j] > 0.f) ? 1.f : 0.f;
            (half ? d_cnt1 : d_cnt0)[b*N + i0 + tid] = c;
        }

        int g2 = tid / 160, n = tid % 160;
        int r0 = g2*3;
        float a0 = 0.f, a1 = 0.f, a2 = 0.f, us = 0.f;
        for (int c = 0; c < 3; c++) {
            __syncthreads();
            const float* src = a + (j0 + c*25)*N;
            for (int idx = tid; idx < 25*N; idx += NT) colS[idx] = src[idx];
            __syncthreads();
            if (n < N) {
                int jb = j0 + c*25;
                #pragma unroll 5
                for (int jj = 0; jj < 25; jj++) {
                    float v = colS[jj*N + n];
                    us += v;
                    a0 += adjS[(r0+0)*N + jb + jj] * v;
                    a1 += adjS[(r0+1)*N + jb + jj] * v;
                    a2 += adjS[(r0+2)*N + jb + jj] * v;
                }
            }
        }
        if (n < N) {
            float* A = half ? d_A1 : d_A0;
            A[b*NN + (i0+r0+0)*N + n] = a0;
            A[b*NN + (i0+r0+1)*N + n] = a1;
            A[b*NN + (i0+r0+2)*N + n] = a2;
            if (g2 == 0 && tile == 0) (half ? d_u1 : d_u0)[b*N + n] = us;
        }
        return;
    }

    // ---- blocks 101..340: Ptmp GEMM, 15-row x 150-col tiles ----
    {
        float* STs = sm;             // 128*20 = 2560
        float* WfS = sm + 2560;      // 16*156 = 2496
        int pb = bid - 1 - ABLK;
        int tile = pb % GT, bt = pb / GT;
        int i0 = tile*RT;

        for (int idx = tid; idx < RT*F; idx += NT) {
            int r = idx >> 7, f = idx & 127;
            int row = bt*N + i0 + r;
            float v = (f < DIN) ? H[row*DIN + f] : E[row*DIN + f - DIN];
            STs[f*RTP + r] = v;
        }
        if (tid < F) STs[tid*RTP + 15] = 0.f;   // pad row

        int j = tid % JT, rg = tid / JT;
        float acc[4][2] = {};
        for (int fc = 0; fc < 8; fc++) {
            __syncthreads();
            // transpose-stage Wfu[:, fc*16 : fc*16+16] -> WfS[ff][m]
            for (int idx = tid; idx < 600; idx += NT) {
                int m = idx >> 2, q = idx & 3;
                float4 w4 = *(const float4*)(Wfu + m*F + fc*16 + q*4);
                int base = (q*4)*WFS + m;
                WfS[base        ] = w4.x;
                WfS[base +   WFS] = w4.y;
                WfS[base + 2*WFS] = w4.z;
                WfS[base + 3*WFS] = w4.w;
            }
            __syncthreads();
            if (j < 75) {
                #pragma unroll
                for (int ff = 0; ff < 16; ff++) {
                    float4 s = *(const float4*)(STs + (fc*16+ff)*RTP + rg*4);
                    float2 w = *(const float2*)(WfS + ff*WFS + 2*j);
                    acc[0][0] += s.x*w.x; acc[0][1] += s.x*w.y;
                    acc[1][0] += s.y*w.x; acc[1][1] += s.y*w.y;
                    acc[2][0] += s.z*w.x; acc[2][1] += s.z*w.y;
                    acc[3][0] += s.w*w.x; acc[3][1] += s.w*w.y;
                }
            }
        }
        if (j < 75) {
            #pragma unroll
            for (int u = 0; u < 4; u++) {
                int r = rg*4 + u;
                if (r < RT) {
                    float2 o = make_float2(acc[u][0], acc[u][1]);
                    *(float2*)(d_Ptmp + bt*NN + (i0+r)*N + 2*j) = o;
                }
            }
        }
    }
}

// ==== K2: g + softmax-closed-form + P = tanh(W @ Ptmp) ====
__global__ __launch_bounds__(NT) void k2(const float* __restrict__ H,
                                         const float* __restrict__ E,
                                         float* __restrict__ out) {
    __shared__ __align__(16) float Ws[N*RTP];   // 12 KB, [k][r]
    __shared__ float gS[32];
    __shared__ float p0s[RT], p1s[RT];
    __shared__ int   flm[RT];
    int tile = blockIdx.x, bt = blockIdx.y, b = bt / TT;
    int tid  = threadIdx.x;
    int i0   = tile*RT;

    // g for the 32 (30 needed) rows (2*i0 + c) % 150
    if (tid < 256) {
        int c = tid >> 3, seg = tid & 7;
        int row = (2*i0 + c) % N;
        int f0 = seg*16;
        const float* src = (f0 < DIN) ? H + (bt*N+row)*DIN + f0
                                      : E + (bt*N+row)*DIN + f0 - DIN;
        float s = 0.f;
        #pragma unroll
        for (int u = 0; u < 16; u++) s += src[u] * d_wg[f0+u];
        s += __shfl_down_sync(0xffffffffu, s, 4);
        s += __shfl_down_sync(0xffffffffu, s, 2);
        s += __shfl_down_sync(0xffffffffu, s, 1);
        if (seg == 0) gS[c] = s + d_cg;
    }
    __syncthreads();

    if (tid < RT) {
        int i = i0 + tid;
        float v0 = gS[2*tid], v1 = gS[2*tid+1];
        float l0 = v0 > 0.f ? v0 : 0.2f*v0;
        float l1 = v1 > 0.f ? v1 : 0.2f*v1;
        float c0 = d_cnt0[b*N + i], c1 = d_cnt1[b*N + i];
        if (c0 + c1 > 0.f) {
            float mx = fmaxf(l0, l1);
            float e0 = expf(l0 - mx), e1 = expf(l1 - mx);
            float Z  = c0*e0 + c1*e1;
            p0s[tid] = e0 / Z; p1s[tid] = e1 / Z; flm[tid] = 0;
        } else {
            flm[tid] = 1;          // fully masked row -> uniform softmax -> colsum/N
        }
    }
    if (tid < N) Ws[tid*RTP + 15] = 0.f;    // pad row
    __syncthreads();

    // W tile: Ws[k][r] = p0*A0 + p1*A1  (or colsum/N)
    for (int idx = tid; idx < RT*N; idx += NT) {
        int k = idx % N, r = idx / N;
        float w;
        if (flm[r]) {
            w = (d_u0[b*N + k] + d_u1[b*N + k]) * (1.0f / (float)N);
        } else {
            w = p0s[r] * __ldg(&d_A0[b*NN + (i0+r)*N + k])
              + p1s[r] * __ldg(&d_A1[b*NN + (i0+r)*N + k]);
        }
        Ws[k*RTP + r] = w;
    }
    __syncthreads();

    int j = tid % JT, rg = tid / JT;
    float acc[4][2] = {};
    if (j < 75) {
        const float* pB = d_Ptmp + bt*NN + 2*j;
        const float* wA = Ws + rg*4;
        #pragma unroll 6
        for (int k = 0; k < N; k++) {
            float2 bv = *(const float2*)(pB + k*N);
            float4 s  = *(const float4*)(wA + k*RTP);
            acc[0][0] += s.x*bv.x; acc[0][1] += s.x*bv.y;
            acc[1][0] += s.y*bv.x; acc[1][1] += s.y*bv.y;
            acc[2][0] += s.z*bv.x; acc[2][1] += s.z*bv.y;
            acc[3][0] += s.w*bv.x; acc[3][1] += s.w*bv.y;
        }
        #pragma unroll
        for (int u = 0; u < 4; u++) {
            int r = rg*4 + u;
            if (r < RT) {
                float2 o = make_float2(tanhf(acc[u][0]), tanhf(acc[u][1]));
                *(float2*)(out + (bt*N + i0 + r)*N + 2*j) = o;
            }
        }
    }
}

// ---------------- launcher ----------------
extern "C" void kernel_launch(void* const* d_in, const int* in_sizes, int n_in,
                              void* d_out, int out_size) {
    const float* H   = (const float*)d_in[0];
    const float* E   = (const float*)d_in[1];
    const float* adj = (const float*)d_in[2];
    const float* WBw = (const float*)d_in[3];
    const float* WBb = (const float*)d_in[4];
    const float* Wfu = (const float*)d_in[5];
    const float* aw  = (const float*)d_in[6];
    float* out = (float*)d_out;

    k1<<<K1G, NT>>>(H, E, adj, WBw, WBb, Wfu, aw);
    k2<<<dim3(GT, B), NT>>>(H, E, out);
}

// round 7
// speedup vs baseline: 1.1629x; 1.1629x over previous
#include <cuda_runtime.h>

#define BS  2
#define TT  12
#define B   24
#define N   150
#define DIN 64
#define F   128
#define NN  (N*N)     // 22500

#define RT   15       // output rows per GEMM tile
#define RTP  20       // padded row stride (LDS.128-aligned)
#define GT   10       // N/RT tiles
#define JT   80       // col-thread slots (j<75 active, 2 cols each)
#define NT   320      // threads per block
#define WFS  156      // WfS row stride
#define ABLK 100      // A-blocks: 25 tiles x 2 halves x 2 b
#define K1G  (1 + ABLK + GT*B)   // 341
#define KCH  25       // k-chunk for k2 mainloop

// ---------------- scratch ----------------
__device__ float d_Ptmp[B*NN];
__device__ float d_A0[BS*NN];
__device__ float d_A1[BS*NN];
__device__ float d_wg[F];
__device__ float d_cg;
__device__ float d_cnt0[BS*N];
__device__ float d_cnt1[BS*N];
__device__ float d_u0[BS*N];
__device__ float d_u1[BS*N];

// ==== K1: wg fold | A0/A1 + counts + colsums | Ptmp GEMM  (one launch) ====
__global__ __launch_bounds__(NT) void k1(
        const float* __restrict__ H, const float* __restrict__ E,
        const float* __restrict__ adj,
        const float* __restrict__ WBw, const float* __restrict__ WBb,
        const float* __restrict__ Wfu, const float* __restrict__ aw) {
    __shared__ __align__(16) float sm[5184];   // 20.7 KB union
    int bid = blockIdx.x, tid = threadIdx.x;

    // ---- block 0: fold wg = WBw^T (aw[:64]+aw[64:]), cg ----
    if (bid == 0) {
        if (tid < F) {
            float acc = 0.f;
            #pragma unroll 8
            for (int h = 0; h < 64; h++)
                acc += WBw[h*F + tid] * (aw[h] + aw[h+64]);
            d_wg[tid] = acc;
        } else if (tid == F) {
            float acc = 0.f;
            for (int h = 0; h < 64; h++) acc += WBb[h] * (aw[h] + aw[h+64]);
            d_cg = acc;
        }
        return;
    }

    // ---- blocks 1..100: A-half blocks ----
    if (bid <= ABLK) {
        float* adjS = sm;            // 900
        float* colS = sm + 900;      // 3750
        int ab = bid - 1;
        int tile = ab % 25, half = (ab / 25) & 1, b = ab / 50;
        const float* a = adj + b*NN;
        int i0 = tile*6, j0 = half*75;

        for (int idx = tid; idx < 6*N; idx += NT) adjS[idx] = a[i0*N + idx];
        __syncthreads();

        if (tid < 6) {
            float c = 0.f;
            #pragma unroll 5
            for (int j = 0; j < 75; j++)
                c += (adjS[tid*N + j0 + j] > 0.f) ? 1.f : 0.f;
            (half ? d_cnt1 : d_cnt0)[b*N + i0 + tid] = c;
        }

        int g2 = tid / 160, n = tid % 160;
        int r0 = g2*3;
        float a0 = 0.f, a1 = 0.f, a2 = 0.f, us = 0.f;
        for (int c = 0; c < 3; c++) {
            __syncthreads();
            const float* src = a + (j0 + c*25)*N;
            for (int idx = tid; idx < 25*N; idx += NT) colS[idx] = src[idx];
            __syncthreads();
            if (n < N) {
                int jb = j0 + c*25;
                #pragma unroll 5
                for (int jj = 0; jj < 25; jj++) {
                    float v = colS[jj*N + n];
                    us += v;
                    a0 += adjS[(r0+0)*N + jb + jj] * v;
                    a1 += adjS[(r0+1)*N + jb + jj] * v;
                    a2 += adjS[(r0+2)*N + jb + jj] * v;
                }
            }
        }
        if (n < N) {
            float* A = half ? d_A1 : d_A0;
            A[b*NN + (i0+r0+0)*N + n] = a0;
            A[b*NN + (i0+r0+1)*N + n] = a1;
            A[b*NN + (i0+r0+2)*N + n] = a2;
            if (g2 == 0 && tile == 0) (half ? d_u1 : d_u0)[b*N + n] = us;
        }
        return;
    }

    // ---- blocks 101..340: Ptmp GEMM, 15-row x 150-col tiles ----
    {
        float* STs = sm;             // 128*20 = 2560
        float* WfS = sm + 2560;      // 16*156 = 2496
        int pb = bid - 1 - ABLK;
        int tile = pb % GT, bt = pb / GT;
        int i0 = tile*RT;

        for (int idx = tid; idx < RT*F; idx += NT) {
            int r = idx >> 7, f = idx & 127;
            int row = bt*N + i0 + r;
            float v = (f < DIN) ? H[row*DIN + f] : E[row*DIN + f - DIN];
            STs[f*RTP + r] = v;
        }
        if (tid < F) STs[tid*RTP + 15] = 0.f;   // pad row

        int j = tid % JT, rg = tid / JT;
        float acc[4][2] = {};
        for (int fc = 0; fc < 8; fc++) {
            __syncthreads();
            // transpose-stage Wfu[:, fc*16 : fc*16+16] -> WfS[ff][m]
            for (int idx = tid; idx < 600; idx += NT) {
                int m = idx >> 2, q = idx & 3;
                float4 w4 = *(const float4*)(Wfu + m*F + fc*16 + q*4);
                int base = (q*4)*WFS + m;
                WfS[base        ] = w4.x;
                WfS[base +   WFS] = w4.y;
                WfS[base + 2*WFS] = w4.z;
                WfS[base + 3*WFS] = w4.w;
            }
            __syncthreads();
            if (j < 75) {
                #pragma unroll
                for (int ff = 0; ff < 16; ff++) {
                    float4 s = *(const float4*)(STs + (fc*16+ff)*RTP + rg*4);
                    float2 w = *(const float2*)(WfS + ff*WFS + 2*j);
                    acc[0][0] += s.x*w.x; acc[0][1] += s.x*w.y;
                    acc[1][0] += s.y*w.x; acc[1][1] += s.y*w.y;
                    acc[2][0] += s.z*w.x; acc[2][1] += s.z*w.y;
                    acc[3][0] += s.w*w.x; acc[3][1] += s.w*w.y;
                }
            }
        }
        if (j < 75) {
            #pragma unroll
            for (int u = 0; u < 4; u++) {
                int r = rg*4 + u;
                if (r < RT) {
                    float2 o = make_float2(acc[u][0], acc[u][1]);
                    *(float2*)(d_Ptmp + bt*NN + (i0+r)*N + 2*j) = o;
                }
            }
        }
    }
}

// ==== K2: g + softmax-closed-form + P = tanh(W @ Ptmp), smem-staged mainloop ====
__global__ __launch_bounds__(NT) void k2(const float* __restrict__ H,
                                         const float* __restrict__ E,
                                         float* __restrict__ out) {
    __shared__ __align__(16) float Ws[N*RTP];    // 12 KB, [k][r]
    __shared__ __align__(16) float PtS[KCH*N];   // 15 KB, [kk][j]
    __shared__ float gS[32];
    __shared__ float p0s[RT], p1s[RT];
    __shared__ int   flm[RT];
    int tile = blockIdx.x, bt = blockIdx.y, b = bt / TT;
    int tid  = threadIdx.x;
    int i0   = tile*RT;

    // g for the 32 (30 needed) rows (2*i0 + c) % 150
    if (tid < 256) {
        int c = tid >> 3, seg = tid & 7;
        int row = (2*i0 + c) % N;
        int f0 = seg*16;
        const float* src = (f0 < DIN) ? H + (bt*N+row)*DIN + f0
                                      : E + (bt*N+row)*DIN + f0 - DIN;
        float s = 0.f;
        #pragma unroll
        for (int u = 0; u < 16; u++) s += src[u] * d_wg[f0+u];
        s += __shfl_down_sync(0xffffffffu, s, 4);
        s += __shfl_down_sync(0xffffffffu, s, 2);
        s += __shfl_down_sync(0xffffffffu, s, 1);
        if (seg == 0) gS[c] = s + d_cg;
    }
    __syncthreads();

    if (tid < RT) {
        int i = i0 + tid;
        float v0 = gS[2*tid], v1 = gS[2*tid+1];
        float l0 = v0 > 0.f ? v0 : 0.2f*v0;
        float l1 = v1 > 0.f ? v1 : 0.2f*v1;
        float c0 = d_cnt0[b*N + i], c1 = d_cnt1[b*N + i];
        if (c0 + c1 > 0.f) {
            float mx = fmaxf(l0, l1);
            float e0 = expf(l0 - mx), e1 = expf(l1 - mx);
            float Z  = c0*e0 + c1*e1;
            p0s[tid] = e0 / Z; p1s[tid] = e1 / Z; flm[tid] = 0;
        } else {
            flm[tid] = 1;          // fully masked row -> uniform softmax -> colsum/N
        }
    }
    if (tid < N) Ws[tid*RTP + 15] = 0.f;    // pad row
    __syncthreads();

    // W tile: Ws[k][r] = p0*A0 + p1*A1  (or colsum/N)
    for (int idx = tid; idx < RT*N; idx += NT) {
        int k = idx % N, r = idx / N;
        float w;
        if (flm[r]) {
            w = (d_u0[b*N + k] + d_u1[b*N + k]) * (1.0f / (float)N);
        } else {
            w = p0s[r] * __ldg(&d_A0[b*NN + (i0+r)*N + k])
              + p1s[r] * __ldg(&d_A1[b*NN + (i0+r)*N + k]);
        }
        Ws[k*RTP + r] = w;
    }

    int j = tid % JT, rg = tid / JT;
    float acc[4][2] = {};
    for (int kc = 0; kc < 6; kc++) {
        __syncthreads();
        // bulk-stage 25 rows of Ptmp (coalesced, high-MLP)
        const float* src = d_Ptmp + bt*NN + kc*KCH*N;
        for (int idx = tid; idx < KCH*N; idx += NT) PtS[idx] = src[idx];
        __syncthreads();
        if (j < 75) {
            const float* wA = Ws + kc*KCH*RTP + rg*4;
            const float* pB = PtS + 2*j;
            #pragma unroll 5
            for (int kk = 0; kk < KCH; kk++) {
                float4 s  = *(const float4*)(wA + kk*RTP);
                float2 bv = *(const float2*)(pB + kk*N);
                acc[0][0] += s.x*bv.x; acc[0][1] += s.x*bv.y;
                acc[1][0] += s.y*bv.x; acc[1][1] += s.y*bv.y;
                acc[2][0] += s.z*bv.x; acc[2][1] += s.z*bv.y;
                acc[3][0] += s.w*bv.x; acc[3][1] += s.w*bv.y;
            }
        }
    }
    if (j < 75) {
        #pragma unroll
        for (int u = 0; u < 4; u++) {
            int r = rg*4 + u;
            if (r < RT) {
                float2 o = make_float2(tanhf(acc[u][0]), tanhf(acc[u][1]));
                *(float2*)(out + (bt*N + i0 + r)*N + 2*j) = o;
            }
        }
    }
}

// ---------------- launcher ----------------
extern "C" void kernel_launch(void* const* d_in, const int* in_sizes, int n_in,
                              void* d_out, int out_size) {
    const float* H   = (const float*)d_in[0];
    const float* E   = (const float*)d_in[1];
    const float* adj = (const float*)d_in[2];
    const float* WBw = (const float*)d_in[3];
    const float* WBb = (const float*)d_in[4];
    const float* Wfu = (const float*)d_in[5];
    const float* aw  = (const float*)d_in[6];
    float* out = (float*)d_out;

    k1<<<K1G, NT>>>(H, E, adj, WBw, WBb, Wfu, aw);
    k2<<<dim3(GT, B), NT>>>(H, E, out);
}

// round 8
// speedup vs baseline: 1.3393x; 1.1517x over previous
#include <cuda_runtime.h>

#define BS  2
#define TT  12
#define B   24
#define N   150
#define DIN 64
#define F   128
#define NN  (N*N)     // 22500

#define RT   15       // output rows per GEMM tile
#define RTP  20       // padded row stride (LDS.128-aligned)
#define GT   10       // N/RT tiles
#define JT   80       // col-thread slots (j<75 active, 2 cols each)
#define NT   320      // threads per block (k1)
#define NT2  640      // threads per block (k2): 2 k-groups of 320
#define WFS  156      // WfS row stride
#define ABLK 100      // A-blocks: 25 tiles x 2 halves x 2 b
#define K1G  (1 + ABLK + GT*B)   // 341
#define KCH  25       // k-chunk for k2 mainloop

// ---------------- scratch ----------------
__device__ float d_Ptmp[B*NN];
__device__ float d_A0[BS*NN];
__device__ float d_A1[BS*NN];
__device__ float d_wg[F];
__device__ float d_cg;
__device__ float d_cnt0[BS*N];
__device__ float d_cnt1[BS*N];
__device__ float d_u0[BS*N];
__device__ float d_u1[BS*N];

// ==== K1: wg fold | A0/A1 + counts + colsums | Ptmp GEMM  (one launch) ====
__global__ __launch_bounds__(NT) void k1(
        const float* __restrict__ H, const float* __restrict__ E,
        const float* __restrict__ adj,
        const float* __restrict__ WBw, const float* __restrict__ WBb,
        const float* __restrict__ Wfu, const float* __restrict__ aw) {
    __shared__ __align__(16) float sm[5184];   // 20.7 KB union
    int bid = blockIdx.x, tid = threadIdx.x;

    // ---- block 0: fold wg = WBw^T (aw[:64]+aw[64:]), cg ----
    if (bid == 0) {
        if (tid < F) {
            float acc = 0.f;
            #pragma unroll 8
            for (int h = 0; h < 64; h++)
                acc += WBw[h*F + tid] * (aw[h] + aw[h+64]);
            d_wg[tid] = acc;
        } else if (tid == F) {
            float acc = 0.f;
            for (int h = 0; h < 64; h++) acc += WBb[h] * (aw[h] + aw[h+64]);
            d_cg = acc;
        }
        return;
    }

    // ---- blocks 1..100: A-half blocks ----
    if (bid <= ABLK) {
        float* adjS = sm;            // 900
        float* colS = sm + 900;      // 3750
        int ab = bid - 1;
        int tile = ab % 25, half = (ab / 25) & 1, b = ab / 50;
        const float* a = adj + b*NN;
        int i0 = tile*6, j0 = half*75;

        for (int idx = tid; idx < 6*N; idx += NT) adjS[idx] = a[i0*N + idx];
        __syncthreads();

        if (tid < 6) {
            float c = 0.f;
            #pragma unroll 5
            for (int j = 0; j < 75; j++)
                c += (adjS[tid*N + j0 + j] > 0.f) ? 1.f : 0.f;
            (half ? d_cnt1 : d_cnt0)[b*N + i0 + tid] = c;
        }

        int g2 = tid / 160, n = tid % 160;
        int r0 = g2*3;
        float a0 = 0.f, a1 = 0.f, a2 = 0.f, us = 0.f;
        for (int c = 0; c < 3; c++) {
            __syncthreads();
            const float* src = a + (j0 + c*25)*N;
            for (int idx = tid; idx < 25*N; idx += NT) colS[idx] = src[idx];
            __syncthreads();
            if (n < N) {
                int jb = j0 + c*25;
                #pragma unroll 5
                for (int jj = 0; jj < 25; jj++) {
                    float v = colS[jj*N + n];
                    us += v;
                    a0 += adjS[(r0+0)*N + jb + jj] * v;
                    a1 += adjS[(r0+1)*N + jb + jj] * v;
                    a2 += adjS[(r0+2)*N + jb + jj] * v;
                }
            }
        }
        if (n < N) {
            float* A = half ? d_A1 : d_A0;
            A[b*NN + (i0+r0+0)*N + n] = a0;
            A[b*NN + (i0+r0+1)*N + n] = a1;
            A[b*NN + (i0+r0+2)*N + n] = a2;
            if (g2 == 0 && tile == 0) (half ? d_u1 : d_u0)[b*N + n] = us;
        }
        return;
    }

    // ---- blocks 101..340: Ptmp GEMM, 15-row x 150-col tiles ----
    {
        float* STs = sm;             // 128*20 = 2560
        float* WfS = sm + 2560;      // 16*156 = 2496
        int pb = bid - 1 - ABLK;
        int tile = pb % GT, bt = pb / GT;
        int i0 = tile*RT;

        for (int idx = tid; idx < RT*F; idx += NT) {
            int r = idx >> 7, f = idx & 127;
            int row = bt*N + i0 + r;
            float v = (f < DIN) ? H[row*DIN + f] : E[row*DIN + f - DIN];
            STs[f*RTP + r] = v;
        }
        if (tid < F) STs[tid*RTP + 15] = 0.f;   // pad row

        int j = tid % JT, rg = tid / JT;
        float acc[4][2] = {};
        for (int fc = 0; fc < 8; fc++) {
            __syncthreads();
            // transpose-stage Wfu[:, fc*16 : fc*16+16] -> WfS[ff][m]
            for (int idx = tid; idx < 600; idx += NT) {
                int m = idx >> 2, q = idx & 3;
                float4 w4 = *(const float4*)(Wfu + m*F + fc*16 + q*4);
                int base = (q*4)*WFS + m;
                WfS[base        ] = w4.x;
                WfS[base +   WFS] = w4.y;
                WfS[base + 2*WFS] = w4.z;
                WfS[base + 3*WFS] = w4.w;
            }
            __syncthreads();
            if (j < 75) {
                #pragma unroll
                for (int ff = 0; ff < 16; ff++) {
                    float4 s = *(const float4*)(STs + (fc*16+ff)*RTP + rg*4);
                    float2 w = *(const float2*)(WfS + ff*WFS + 2*j);
                    acc[0][0] += s.x*w.x; acc[0][1] += s.x*w.y;
                    acc[1][0] += s.y*w.x; acc[1][1] += s.y*w.y;
                    acc[2][0] += s.z*w.x; acc[2][1] += s.z*w.y;
                    acc[3][0] += s.w*w.x; acc[3][1] += s.w*w.y;
                }
            }
        }
        if (j < 75) {
            #pragma unroll
            for (int u = 0; u < 4; u++) {
                int r = rg*4 + u;
                if (r < RT) {
                    float2 o = make_float2(acc[u][0], acc[u][1]);
                    *(float2*)(d_Ptmp + bt*NN + (i0+r)*N + 2*j) = o;
                }
            }
        }
    }
}

// ==== K2: g + softmax + P = tanh(W @ Ptmp); 640 thr, in-block k-split x2 ====
__global__ __launch_bounds__(NT2) void k2(const float* __restrict__ H,
                                          const float* __restrict__ E,
                                          float* __restrict__ out) {
    __shared__ __align__(16) float Ws[N*RTP];      // 12 KB, [k][r]
    __shared__ __align__(16) float PtS[2*KCH*N];   // 30 KB, per-group chunk
    __shared__ float gS[32];
    __shared__ float p0s[RT], p1s[RT];
    __shared__ int   flm[RT];
    int tile = blockIdx.x, bt = blockIdx.y, b = bt / TT;
    int tid  = threadIdx.x;
    int i0   = tile*RT;

    // g for the 32 (30 needed) rows (2*i0 + c) % 150
    if (tid < 256) {
        int c = tid >> 3, seg = tid & 7;
        int row = (2*i0 + c) % N;
        int f0 = seg*16;
        const float* src = (f0 < DIN) ? H + (bt*N+row)*DIN + f0
                                      : E + (bt*N+row)*DIN + f0 - DIN;
        float s = 0.f;
        #pragma unroll
        for (int u = 0; u < 16; u++) s += src[u] * d_wg[f0+u];
        s += __shfl_down_sync(0xffffffffu, s, 4);
        s += __shfl_down_sync(0xffffffffu, s, 2);
        s += __shfl_down_sync(0xffffffffu, s, 1);
        if (seg == 0) gS[c] = s + d_cg;
    }
    __syncthreads();

    if (tid < RT) {
        int i = i0 + tid;
        float v0 = gS[2*tid], v1 = gS[2*tid+1];
        float l0 = v0 > 0.f ? v0 : 0.2f*v0;
        float l1 = v1 > 0.f ? v1 : 0.2f*v1;
        float c0 = d_cnt0[b*N + i], c1 = d_cnt1[b*N + i];
        if (c0 + c1 > 0.f) {
            float mx = fmaxf(l0, l1);
            float e0 = expf(l0 - mx), e1 = expf(l1 - mx);
            float Z  = c0*e0 + c1*e1;
            p0s[tid] = e0 / Z; p1s[tid] = e1 / Z; flm[tid] = 0;
        } else {
            flm[tid] = 1;          // fully masked row -> uniform softmax -> colsum/N
        }
    }
    if (tid < N) Ws[tid*RTP + 15] = 0.f;    // pad row
    __syncthreads();

    // W tile: Ws[k][r] = p0*A0 + p1*A1  (or colsum/N)
    for (int idx = tid; idx < RT*N; idx += NT2) {
        int k = idx % N, r = idx / N;
        float w;
        if (flm[r]) {
            w = (d_u0[b*N + k] + d_u1[b*N + k]) * (1.0f / (float)N);
        } else {
            w = p0s[r] * __ldg(&d_A0[b*NN + (i0+r)*N + k])
              + p1s[r] * __ldg(&d_A1[b*NN + (i0+r)*N + k]);
        }
        Ws[k*RTP + r] = w;
    }
    __syncthreads();

    int kh = tid / NT;          // k-group 0/1
    int t  = tid % NT;
    int j  = t % JT, rg = t / JT;
    int barid = kh + 1;
    float* P = PtS + kh*(KCH*N);

    float acc[4][2] = {};
    for (int kc = 0; kc < 3; kc++) {
        int k0 = kh*75 + kc*KCH;
        asm volatile("bar.sync %0, %1;" :: "r"(barid), "r"(NT) : "memory");
        const float* src = d_Ptmp + bt*NN + k0*N;
        for (int idx = t; idx < KCH*N; idx += NT) P[idx] = src[idx];
        asm volatile("bar.sync %0, %1;" :: "r"(barid), "r"(NT) : "memory");
        if (j < 75) {
            const float* wA = Ws + k0*RTP + rg*4;
            const float* pB = P + 2*j;
            #pragma unroll 5
            for (int kk = 0; kk < KCH; kk++) {
                float4 s  = *(const float4*)(wA + kk*RTP);
                float2 bv = *(const float2*)(pB + kk*N);
                acc[0][0] += s.x*bv.x; acc[0][1] += s.x*bv.y;
                acc[1][0] += s.y*bv.x; acc[1][1] += s.y*bv.y;
                acc[2][0] += s.z*bv.x; acc[2][1] += s.z*bv.y;
                acc[3][0] += s.w*bv.x; acc[3][1] += s.w*bv.y;
            }
        }
    }

    // cross-group reduce: group 1 dumps into its (dead) staging buffer
    __syncthreads();
    float* red = PtS + KCH*N;
    if (kh == 1 && j < 75) {
        #pragma unroll
        for (int u = 0; u < 4; u++) {
            int r = rg*4 + u;
            if (r < RT) {
                red[r*N + 2*j]     = acc[u][0];
                red[r*N + 2*j + 1] = acc[u][1];
            }
        }
    }
    __syncthreads();
    if (kh == 0 && j < 75) {
        #pragma unroll
        for (int u = 0; u < 4; u++) {
            int r = rg*4 + u;
            if (r < RT) {
                float2 o = make_float2(tanhf(acc[u][0] + red[r*N + 2*j]),
                                       tanhf(acc[u][1] + red[r*N + 2*j + 1]));
                *(float2*)(out + (bt*N + i0 + r)*N + 2*j) = o;
            }
        }
    }
}

// ---------------- launcher ----------------
extern "C" void kernel_launch(void* const* d_in, const int* in_sizes, int n_in,
                              void* d_out, int out_size) {
    const float* H   = (const float*)d_in[0];
    const float* E   = (const float*)d_in[1];
    const float* adj = (const float*)d_in[2];
    const float* WBw = (const float*)d_in[3];
    const float* WBb = (const float*)d_in[4];
    const float* Wfu = (const float*)d_in[5];
    const float* aw  = (const float*)d_in[6];
    float* out = (float*)d_out;

    k1<<<K1G, NT>>>(H, E, adj, WBw, WBb, Wfu, aw);
    k2<<<dim3(GT, B), NT2>>>(H, E, out);
}